// round 1
// baseline (speedup 1.0000x reference)
#include <cuda_runtime.h>
#include <math.h>

#define BB   256
#define DD   256
#define HH   512
#define EE   64
#define NLF  1024
#define KOUT 10

// ---------------- scratch (device globals; no allocation allowed) ----------
__device__ float g_Y1[BB * HH];
__device__ float g_Y2[BB * HH];
__device__ float g_h1[BB * HH];
__device__ float g_h2[BB * HH];
__device__ float g_logits[BB * NLF];
__device__ int   g_bidx[BB];
__device__ float g_rootlp[BB];
__device__ int   g_count[EE];
__device__ int   g_slot[EE * BB];

// ---------------- 0: zero routing counts -----------------------------------
__global__ void k_zero()
{
    if (threadIdx.x < EE) g_count[threadIdx.x] = 0;
}

// ---------------- root dense layers (relu(X @ W + b)) ----------------------
// block: 256 threads -> 16 samples x 64 outputs. grid (B/16, H/64)
template <int KDIM, int SRCSEL, int DSTSEL>
__global__ __launch_bounds__(256) void k_root_linear(
    const float* __restrict__ Xin, const float* __restrict__ W,
    const float* __restrict__ bias)
{
    const float* X = (SRCSEL == 0) ? Xin : g_Y1;
    float* Y = (DSTSEL == 0) ? g_Y1 : g_Y2;
    const int OT = HH;

    __shared__ float4 sX[16][KDIM / 4];
    int s0 = blockIdx.x * 16;
    int tx = threadIdx.x & 63;
    int ty = threadIdx.x >> 6;           // 0..3 -> sample subgroup
    int o  = blockIdx.y * 64 + tx;

    for (int i = threadIdx.x; i < 16 * (KDIM / 4); i += 256) {
        int s = i / (KDIM / 4), kk = i % (KDIM / 4);
        sX[s][kk] = reinterpret_cast<const float4*>(X + (size_t)(s0 + s) * KDIM)[kk];
    }
    __syncthreads();

    float acc0 = 0.f, acc1 = 0.f, acc2 = 0.f, acc3 = 0.f;
#pragma unroll 2
    for (int k4 = 0; k4 < KDIM / 4; k4++) {
        float w0 = W[(size_t)(k4 * 4 + 0) * OT + o];
        float w1 = W[(size_t)(k4 * 4 + 1) * OT + o];
        float w2 = W[(size_t)(k4 * 4 + 2) * OT + o];
        float w3 = W[(size_t)(k4 * 4 + 3) * OT + o];
        float4 x0 = sX[ty * 4 + 0][k4];
        float4 x1 = sX[ty * 4 + 1][k4];
        float4 x2 = sX[ty * 4 + 2][k4];
        float4 x3 = sX[ty * 4 + 3][k4];
        acc0 = fmaf(w0, x0.x, acc0); acc0 = fmaf(w1, x0.y, acc0);
        acc0 = fmaf(w2, x0.z, acc0); acc0 = fmaf(w3, x0.w, acc0);
        acc1 = fmaf(w0, x1.x, acc1); acc1 = fmaf(w1, x1.y, acc1);
        acc1 = fmaf(w2, x1.z, acc1); acc1 = fmaf(w3, x1.w, acc1);
        acc2 = fmaf(w0, x2.x, acc2); acc2 = fmaf(w1, x2.y, acc2);
        acc2 = fmaf(w2, x2.z, acc2); acc2 = fmaf(w3, x2.w, acc2);
        acc3 = fmaf(w0, x3.x, acc3); acc3 = fmaf(w1, x3.y, acc3);
        acc3 = fmaf(w2, x3.z, acc3); acc3 = fmaf(w3, x3.w, acc3);
    }
    float bb = bias[o];
    Y[(size_t)(s0 + ty * 4 + 0) * OT + o] = fmaxf(acc0 + bb, 0.f);
    Y[(size_t)(s0 + ty * 4 + 1) * OT + o] = fmaxf(acc1 + bb, 0.f);
    Y[(size_t)(s0 + ty * 4 + 2) * OT + o] = fmaxf(acc2 + bb, 0.f);
    Y[(size_t)(s0 + ty * 4 + 3) * OT + o] = fmaxf(acc3 + bb, 0.f);
}

// ---------------- root head: logits[B,E], argmax, log_softmax, routing -----
// block: 4 samples x 64 experts = 256 threads. grid (B/4)
__global__ __launch_bounds__(256) void k_root_head(
    const float* __restrict__ W, const float* __restrict__ bias)
{
    __shared__ float4 sX[4][HH / 4];
    __shared__ float  slog[4][EE];

    int s0 = blockIdx.x * 4;
    int e  = threadIdx.x & 63;
    int sj = threadIdx.x >> 6;

    for (int i = threadIdx.x; i < 4 * (HH / 4); i += 256) {
        int s = i / (HH / 4), kk = i % (HH / 4);
        sX[s][kk] = reinterpret_cast<const float4*>(g_Y2 + (size_t)(s0 + s) * HH)[kk];
    }
    __syncthreads();

    float acc = 0.f;
#pragma unroll 4
    for (int k4 = 0; k4 < HH / 4; k4++) {
        float4 x = sX[sj][k4];
        acc = fmaf(W[(size_t)(k4 * 4 + 0) * EE + e], x.x, acc);
        acc = fmaf(W[(size_t)(k4 * 4 + 1) * EE + e], x.y, acc);
        acc = fmaf(W[(size_t)(k4 * 4 + 2) * EE + e], x.z, acc);
        acc = fmaf(W[(size_t)(k4 * 4 + 3) * EE + e], x.w, acc);
    }
    slog[sj][e] = acc + bias[e];
    __syncthreads();

    if (e == 0) {
        float mx = slog[sj][0];
        int   mi = 0;
        for (int i = 1; i < EE; i++) {
            float v = slog[sj][i];
            if (v > mx) { mx = v; mi = i; }      // strict > : ties -> lowest index
        }
        float se = 0.f;
        for (int i = 0; i < EE; i++) se += __expf(slog[sj][i] - mx);
        int b = s0 + sj;
        g_bidx[b]   = mi;
        g_rootlp[b] = slog[sj][mi] - mx - __logf(se);
        int pos = atomicAdd(&g_count[mi], 1);
        g_slot[mi * BB + pos] = b;
    }
}

// ---------------- expert layer compute tile ---------------------------------
template <int KDIM, int CMAX, bool RELU>
__device__ __forceinline__ void exp_tile(
    const float* __restrict__ W, int OT, int o, float bb, int ct,
    const float4 (*sX)[KDIM / 4], const int* sB, float* __restrict__ Y)
{
    float acc[CMAX];
#pragma unroll
    for (int j = 0; j < CMAX; j++) acc[j] = 0.f;

#pragma unroll 2
    for (int k4 = 0; k4 < KDIM / 4; k4++) {
        float w0 = W[(size_t)(k4 * 4 + 0) * OT + o];
        float w1 = W[(size_t)(k4 * 4 + 1) * OT + o];
        float w2 = W[(size_t)(k4 * 4 + 2) * OT + o];
        float w3 = W[(size_t)(k4 * 4 + 3) * OT + o];
#pragma unroll
        for (int j = 0; j < CMAX; j++) {
            float4 x = sX[j][k4];
            acc[j] = fmaf(w0, x.x, acc[j]);
            acc[j] = fmaf(w1, x.y, acc[j]);
            acc[j] = fmaf(w2, x.z, acc[j]);
            acc[j] = fmaf(w3, x.w, acc[j]);
        }
    }
#pragma unroll
    for (int j = 0; j < CMAX; j++) {
        if (j < ct) {
            float v = acc[j] + bb;
            if (RELU) v = fmaxf(v, 0.f);
            Y[(size_t)sB[j] * OT + o] = v;
        }
    }
}

// ---------------- grouped expert dense layer --------------------------------
// block = (expert, 256-output chunk); streams this expert's weight slice once
// per sample tile (tile = 16 samples; typical count ~4 so one tile).
template <int KDIM, int SRCSEL, int DSTSEL, int OT, bool RELU>
__global__ __launch_bounds__(256) void k_expert(
    const float* __restrict__ Xin, const float* __restrict__ Wsrc,
    const float* __restrict__ bsrc)
{
    const float* X = (SRCSEL == 0) ? Xin : ((SRCSEL == 1) ? g_h1 : g_h2);
    float* Y = (DSTSEL == 0) ? g_h1 : ((DSTSEL == 1) ? g_h2 : g_logits);

    int ex = blockIdx.x;
    int c  = g_count[ex];
    if (c == 0) return;

    int o = blockIdx.y * 256 + threadIdx.x;
    const float* W = Wsrc + (size_t)ex * KDIM * OT;
    float bb = bsrc[(size_t)ex * OT + o];

    __shared__ float4 sX[16][KDIM / 4];
    __shared__ int    sB[16];

    for (int st = 0; st < c; st += 16) {
        int ct = min(16, c - st);
        __syncthreads();                       // protect prior-tile sX reads
        if (threadIdx.x < 16)
            sB[threadIdx.x] = (threadIdx.x < ct) ? g_slot[ex * BB + st + threadIdx.x] : 0;
        __syncthreads();
        for (int i = threadIdx.x; i < 16 * (KDIM / 4); i += 256) {
            int s = i / (KDIM / 4), kk = i % (KDIM / 4);
            float4 v = make_float4(0.f, 0.f, 0.f, 0.f);
            if (s < ct) v = reinterpret_cast<const float4*>(X + (size_t)sB[s] * KDIM)[kk];
            sX[s][kk] = v;
        }
        __syncthreads();

        if (ct <= 4)      exp_tile<KDIM, 4,  RELU>(W, OT, o, bb, ct, sX, sB, Y);
        else if (ct <= 8) exp_tile<KDIM, 8,  RELU>(W, OT, o, bb, ct, sX, sB, Y);
        else              exp_tile<KDIM, 16, RELU>(W, OT, o, bb, ct, sX, sB, Y);
    }
}

// ---------------- final: log_softmax + top-11 + filter + emit ---------------
__global__ __launch_bounds__(256) void k_final(float* __restrict__ out)
{
    int b = blockIdx.x;
    __shared__ float sv[NLF];
    __shared__ float rv[256];
    __shared__ int   ri[256];
    __shared__ int   chosen[KOUT + 1];

    const float* row = g_logits + (size_t)b * NLF;

    float lmax = -INFINITY;
    for (int i = threadIdx.x; i < NLF; i += 256) {
        float v = row[i];
        sv[i] = v;
        lmax = fmaxf(lmax, v);
    }
    rv[threadIdx.x] = lmax;
    __syncthreads();
    for (int off = 128; off > 0; off >>= 1) {
        if (threadIdx.x < off) rv[threadIdx.x] = fmaxf(rv[threadIdx.x], rv[threadIdx.x + off]);
        __syncthreads();
    }
    float mx = rv[0];
    __syncthreads();

    float lsum = 0.f;
    for (int i = threadIdx.x; i < NLF; i += 256) lsum += __expf(sv[i] - mx);
    rv[threadIdx.x] = lsum;
    __syncthreads();
    for (int off = 128; off > 0; off >>= 1) {
        if (threadIdx.x < off) rv[threadIdx.x] += rv[threadIdx.x + off];
        __syncthreads();
    }
    float lse = mx + __logf(rv[0]);
    __syncthreads();

    // iterative masked argmax: value desc, ties -> lowest index (matches top_k)
    for (int t = 0; t < KOUT + 1; t++) {
        float bv = -INFINITY;
        int   bi = NLF;
        for (int i = threadIdx.x; i < NLF; i += 256) {
            float v = sv[i];
            if (v > bv) { bv = v; bi = i; }    // ascending i scan: keeps lowest idx
        }
        rv[threadIdx.x] = bv;
        ri[threadIdx.x] = bi;
        __syncthreads();
        for (int off = 128; off > 0; off >>= 1) {
            if (threadIdx.x < off) {
                float v2 = rv[threadIdx.x + off];
                int   i2 = ri[threadIdx.x + off];
                if (v2 > rv[threadIdx.x] ||
                    (v2 == rv[threadIdx.x] && i2 < ri[threadIdx.x])) {
                    rv[threadIdx.x] = v2;
                    ri[threadIdx.x] = i2;
                }
            }
            __syncthreads();
        }
        if (threadIdx.x == 0) {
            chosen[t] = ri[0];
            sv[ri[0]] = -INFINITY;
        }
        __syncthreads();
    }

    if (threadIdx.x == 0) {
        int   branch = g_bidx[b];
        float rlp    = g_rootlp[b];
        float* traj  = out;                    // [B][K][2] as float
        float* flp   = out + BB * KOUT * 2;    // [B][K]
        int w = 0;
        for (int t = 0; t < KOUT + 1 && w < KOUT; t++) {
            int item = chosen[t];
            if (item == 0 && branch == 0) continue;   // drop id-0 trajectory
            traj[((size_t)b * KOUT + w) * 2 + 0] = (float)branch;
            traj[((size_t)b * KOUT + w) * 2 + 1] = (float)item;
            flp[(size_t)b * KOUT + w] = (row[item] - lse) + rlp;
            w++;
        }
    }
}

// ---------------- launch ----------------------------------------------------
extern "C" void kernel_launch(void* const* d_in, const int* in_sizes, int n_in,
                              void* d_out, int out_size)
{
    const float* state = (const float*)d_in[0];
    const float* rW1   = (const float*)d_in[1];
    const float* rb1   = (const float*)d_in[2];
    const float* rW2   = (const float*)d_in[3];
    const float* rb2   = (const float*)d_in[4];
    const float* rW3   = (const float*)d_in[5];
    const float* rb3   = (const float*)d_in[6];
    const float* eW1   = (const float*)d_in[7];
    const float* eb1   = (const float*)d_in[8];
    const float* eW2   = (const float*)d_in[9];
    const float* eb2   = (const float*)d_in[10];
    const float* eW3   = (const float*)d_in[11];
    const float* eb3   = (const float*)d_in[12];
    float* out = (float*)d_out;

    k_zero<<<1, 64>>>();
    k_root_linear<DD, 0, 0><<<dim3(BB / 16, HH / 64), 256>>>(state, rW1, rb1);
    k_root_linear<HH, 1, 1><<<dim3(BB / 16, HH / 64), 256>>>(nullptr, rW2, rb2);
    k_root_head<<<BB / 4, 256>>>(rW3, rb3);
    k_expert<DD, 0, 0, HH,  true ><<<dim3(EE, HH  / 256), 256>>>(state,  eW1, eb1);
    k_expert<HH, 1, 1, HH,  true ><<<dim3(EE, HH  / 256), 256>>>(nullptr, eW2, eb2);
    k_expert<HH, 2, 2, NLF, false><<<dim3(EE, NLF / 256), 256>>>(nullptr, eW3, eb3);
    k_final<<<BB, 256>>>(out);
}

// round 2
// speedup vs baseline: 1.8175x; 1.8175x over previous
#include <cuda_runtime.h>
#include <math.h>

#define BB   256
#define DD   256
#define HH   512
#define EE   64
#define NLF  1024
#define KOUT 10

// ---------------- scratch (device globals; no allocation allowed) ----------
__device__ float g_Y1[BB * HH];
__device__ float g_Y2[BB * HH];
__device__ float g_h1[BB * HH];
__device__ float g_h2[BB * HH];
__device__ int   g_bidx[BB];
__device__ float g_rootlp[BB];
__device__ int   g_count[EE];
__device__ int   g_slot[EE * BB];
// k-split partial sums (deterministic; no float atomics)
__device__ float g_p1[4 * BB * HH];    // 2 MB
__device__ float g_p2[4 * BB * HH];    // 2 MB
__device__ float g_p3[8 * BB * NLF];   // 8 MB

// ---------------- 0: zero routing counts -----------------------------------
__global__ void k_zero()
{
    if (threadIdx.x < EE) g_count[threadIdx.x] = 0;
}

// ---------------- root dense layers (relu(X @ W + b)) ----------------------
// block: 256 threads -> 16 samples x 64 outputs. grid (B/16, H/64)
template <int KDIM, int SRCSEL, int DSTSEL>
__global__ __launch_bounds__(256) void k_root_linear(
    const float* __restrict__ Xin, const float* __restrict__ W,
    const float* __restrict__ bias)
{
    const float* X = (SRCSEL == 0) ? Xin : g_Y1;
    float* Y = (DSTSEL == 0) ? g_Y1 : g_Y2;
    const int OT = HH;

    __shared__ float4 sX[16][KDIM / 4];
    int s0 = blockIdx.x * 16;
    int tx = threadIdx.x & 63;
    int ty = threadIdx.x >> 6;           // 0..3 -> sample subgroup
    int o  = blockIdx.y * 64 + tx;

    for (int i = threadIdx.x; i < 16 * (KDIM / 4); i += 256) {
        int s = i / (KDIM / 4), kk = i % (KDIM / 4);
        sX[s][kk] = reinterpret_cast<const float4*>(X + (size_t)(s0 + s) * KDIM)[kk];
    }
    __syncthreads();

    float acc0 = 0.f, acc1 = 0.f, acc2 = 0.f, acc3 = 0.f;
#pragma unroll 4
    for (int k4 = 0; k4 < KDIM / 4; k4++) {
        float w0 = W[(size_t)(k4 * 4 + 0) * OT + o];
        float w1 = W[(size_t)(k4 * 4 + 1) * OT + o];
        float w2 = W[(size_t)(k4 * 4 + 2) * OT + o];
        float w3 = W[(size_t)(k4 * 4 + 3) * OT + o];
        float4 x0 = sX[ty * 4 + 0][k4];
        float4 x1 = sX[ty * 4 + 1][k4];
        float4 x2 = sX[ty * 4 + 2][k4];
        float4 x3 = sX[ty * 4 + 3][k4];
        acc0 = fmaf(w0, x0.x, acc0); acc0 = fmaf(w1, x0.y, acc0);
        acc0 = fmaf(w2, x0.z, acc0); acc0 = fmaf(w3, x0.w, acc0);
        acc1 = fmaf(w0, x1.x, acc1); acc1 = fmaf(w1, x1.y, acc1);
        acc1 = fmaf(w2, x1.z, acc1); acc1 = fmaf(w3, x1.w, acc1);
        acc2 = fmaf(w0, x2.x, acc2); acc2 = fmaf(w1, x2.y, acc2);
        acc2 = fmaf(w2, x2.z, acc2); acc2 = fmaf(w3, x2.w, acc2);
        acc3 = fmaf(w0, x3.x, acc3); acc3 = fmaf(w1, x3.y, acc3);
        acc3 = fmaf(w2, x3.z, acc3); acc3 = fmaf(w3, x3.w, acc3);
    }
    float bb = bias[o];
    Y[(size_t)(s0 + ty * 4 + 0) * OT + o] = fmaxf(acc0 + bb, 0.f);
    Y[(size_t)(s0 + ty * 4 + 1) * OT + o] = fmaxf(acc1 + bb, 0.f);
    Y[(size_t)(s0 + ty * 4 + 2) * OT + o] = fmaxf(acc2 + bb, 0.f);
    Y[(size_t)(s0 + ty * 4 + 3) * OT + o] = fmaxf(acc3 + bb, 0.f);
}

// ---------------- root head: 1 sample per block, 4-way K split --------------
__global__ __launch_bounds__(256) void k_root_head2(
    const float* __restrict__ W, const float* __restrict__ bias)
{
    int b = blockIdx.x;
    int e = threadIdx.x & 63;
    int p = threadIdx.x >> 6;            // 0..3 K-quarter
    __shared__ float red[4][EE];
    __shared__ float slog[EE];

    const float* x  = g_Y2 + (size_t)b * HH + p * (HH / 4);
    const float* wp = W + (size_t)p * (HH / 4) * EE + e;
    float acc = 0.f;
#pragma unroll 8
    for (int k = 0; k < HH / 4; k++)
        acc = fmaf(wp[(size_t)k * EE], x[k], acc);
    red[p][e] = acc;
    __syncthreads();

    if (threadIdx.x < EE) {
        int t = threadIdx.x;
        slog[t] = red[0][t] + red[1][t] + red[2][t] + red[3][t] + bias[t];
    }
    __syncthreads();

    if (threadIdx.x == 0) {
        float mx = slog[0];
        int   mi = 0;
        for (int i = 1; i < EE; i++) {
            float v = slog[i];
            if (v > mx) { mx = v; mi = i; }      // strict > : ties -> lowest index
        }
        float se = 0.f;
        for (int i = 0; i < EE; i++) se += __expf(slog[i] - mx);
        g_bidx[b]   = mi;
        g_rootlp[b] = slog[mi] - mx - __logf(se);
        int pos = atomicAdd(&g_count[mi], 1);
        g_slot[mi * BB + pos] = b;
    }
}

// ---------------- expert tile core: 4 outputs/thread, float4 weights --------
__device__ __forceinline__ void fma4(float4& a, const float4 w, const float s)
{
    a.x = fmaf(w.x, s, a.x); a.y = fmaf(w.y, s, a.y);
    a.z = fmaf(w.z, s, a.z); a.w = fmaf(w.w, s, a.w);
}

template <int KR, int OT, int CM>
__device__ __forceinline__ void exp_core(
    const float* __restrict__ W, int o,
    const float4 (*sX)[KR / 4], const int* sB, int ct,
    float* __restrict__ P)
{
    float4 acc[CM];
#pragma unroll
    for (int j = 0; j < CM; j++) acc[j] = make_float4(0.f, 0.f, 0.f, 0.f);

#pragma unroll 2
    for (int k4 = 0; k4 < KR / 4; k4++) {
        const float* wp = W + (size_t)(k4 * 4) * OT + o;
        float4 w0 = *reinterpret_cast<const float4*>(wp);
        float4 w1 = *reinterpret_cast<const float4*>(wp + OT);
        float4 w2 = *reinterpret_cast<const float4*>(wp + 2 * OT);
        float4 w3 = *reinterpret_cast<const float4*>(wp + 3 * OT);
#pragma unroll
        for (int j = 0; j < CM; j++) {
            float4 x = sX[j][k4];
            fma4(acc[j], w0, x.x);
            fma4(acc[j], w1, x.y);
            fma4(acc[j], w2, x.z);
            fma4(acc[j], w3, x.w);
        }
    }
#pragma unroll
    for (int j = 0; j < CM; j++)
        if (j < ct)
            *reinterpret_cast<float4*>(P + (size_t)sB[j] * OT + o) = acc[j];
}

// ---------------- grouped expert dense layer, K-split partials --------------
// grid (EE, KS); block = OT/4 threads; each block streams W slice once/tile.
template <int KDIM, int KS, int OT, int SRC, int DST>
__global__ __launch_bounds__(256) void k_exp(
    const float* __restrict__ Xin, const float* __restrict__ Wsrc)
{
    constexpr int KR = KDIM / KS;
    const float* X = (SRC == 0) ? Xin : ((SRC == 1) ? g_h1 : g_h2);
    float* Pbase = (DST == 0) ? g_p1 : ((DST == 1) ? g_p2 : g_p3);

    int ex = blockIdx.x, ks = blockIdx.y;
    int c = g_count[ex];
    if (c == 0) return;

    float* P = Pbase + (size_t)ks * BB * OT;
    const float* W = Wsrc + (size_t)ex * KDIM * OT + (size_t)ks * KR * OT;
    int o = threadIdx.x * 4;

    __shared__ float4 sX[8][KR / 4];
    __shared__ int    sB[8];

    for (int st = 0; st < c; st += 8) {
        int ct = min(8, c - st);
        __syncthreads();
        if (threadIdx.x < 8)
            sB[threadIdx.x] = g_slot[ex * BB + st + ((threadIdx.x < ct) ? threadIdx.x : 0)];
        __syncthreads();
        for (int i = threadIdx.x; i < 8 * (KR / 4); i += blockDim.x) {
            int s = i / (KR / 4), kk = i % (KR / 4);
            sX[s][kk] = *reinterpret_cast<const float4*>(
                X + (size_t)sB[s] * KDIM + ks * KR + kk * 4);
        }
        __syncthreads();

        if (ct <= 4) exp_core<KR, OT, 4>(W, o, sX, sB, ct, P);
        else         exp_core<KR, OT, 8>(W, o, sX, sB, ct, P);
    }
}

// ---------------- reduce partials + bias + relu -----------------------------
template <int KS, int OT, int DST>
__global__ __launch_bounds__(256) void k_red(const float* __restrict__ ebias)
{
    const float* Pb = (DST == 0) ? g_p1 : g_p2;
    float* Y = (DST == 0) ? g_h1 : g_h2;
    int idx = blockIdx.x * 256 + threadIdx.x;          // float4 index
    const int row4 = OT / 4;
    int b = idx / row4, o4 = idx % row4;
    int o = o4 * 4;

    float4 s = *reinterpret_cast<const float4*>(Pb + (size_t)b * OT + o);
#pragma unroll
    for (int ks = 1; ks < KS; ks++) {
        float4 v = *reinterpret_cast<const float4*>(Pb + ((size_t)ks * BB + b) * OT + o);
        s.x += v.x; s.y += v.y; s.z += v.z; s.w += v.w;
    }
    float4 bb = *reinterpret_cast<const float4*>(ebias + (size_t)g_bidx[b] * OT + o);
    s.x = fmaxf(s.x + bb.x, 0.f);
    s.y = fmaxf(s.y + bb.y, 0.f);
    s.z = fmaxf(s.z + bb.z, 0.f);
    s.w = fmaxf(s.w + bb.w, 0.f);
    *reinterpret_cast<float4*>(Y + (size_t)b * OT + o) = s;
}

// ---------------- final: fuse L3 reduce + log_softmax + top-11 + emit -------
__global__ __launch_bounds__(256) void k_final(
    float* __restrict__ out, const float* __restrict__ eb3)
{
    int b = blockIdx.x;
    __shared__ float sv[NLF];
    __shared__ float orig[NLF];
    __shared__ float rv[256];
    __shared__ int   ri[256];
    __shared__ int   chosen[KOUT + 1];

    int branch = g_bidx[b];

    float lmax = -INFINITY;
    for (int i = threadIdx.x; i < NLF; i += 256) {
        float v = eb3[(size_t)branch * NLF + i];
#pragma unroll
        for (int ks = 0; ks < 8; ks++)
            v += g_p3[((size_t)ks * BB + b) * NLF + i];
        sv[i] = v;
        orig[i] = v;
        lmax = fmaxf(lmax, v);
    }
    rv[threadIdx.x] = lmax;
    __syncthreads();
    for (int off = 128; off > 0; off >>= 1) {
        if (threadIdx.x < off) rv[threadIdx.x] = fmaxf(rv[threadIdx.x], rv[threadIdx.x + off]);
        __syncthreads();
    }
    float mx = rv[0];
    __syncthreads();

    float lsum = 0.f;
    for (int i = threadIdx.x; i < NLF; i += 256) lsum += __expf(sv[i] - mx);
    rv[threadIdx.x] = lsum;
    __syncthreads();
    for (int off = 128; off > 0; off >>= 1) {
        if (threadIdx.x < off) rv[threadIdx.x] += rv[threadIdx.x + off];
        __syncthreads();
    }
    float lse = mx + __logf(rv[0]);
    __syncthreads();

    // iterative masked argmax: value desc, ties -> lowest index (matches top_k)
    for (int t = 0; t < KOUT + 1; t++) {
        float bv = -INFINITY;
        int   bi = NLF;
        for (int i = threadIdx.x; i < NLF; i += 256) {
            float v = sv[i];
            if (v > bv) { bv = v; bi = i; }    // ascending scan keeps lowest idx
        }
        rv[threadIdx.x] = bv;
        ri[threadIdx.x] = bi;
        __syncthreads();
        for (int off = 128; off > 0; off >>= 1) {
            if (threadIdx.x < off) {
                float v2 = rv[threadIdx.x + off];
                int   i2 = ri[threadIdx.x + off];
                if (v2 > rv[threadIdx.x] ||
                    (v2 == rv[threadIdx.x] && i2 < ri[threadIdx.x])) {
                    rv[threadIdx.x] = v2;
                    ri[threadIdx.x] = i2;
                }
            }
            __syncthreads();
        }
        if (threadIdx.x == 0) {
            chosen[t] = ri[0];
            sv[ri[0]] = -INFINITY;
        }
        __syncthreads();
    }

    if (threadIdx.x == 0) {
        float rlp   = g_rootlp[b];
        float* traj = out;                    // [B][K][2] as float
        float* flp  = out + BB * KOUT * 2;    // [B][K]
        int w = 0;
        for (int t = 0; t < KOUT + 1 && w < KOUT; t++) {
            int item = chosen[t];
            if (item == 0 && branch == 0) continue;   // drop id-0 trajectory
            traj[((size_t)b * KOUT + w) * 2 + 0] = (float)branch;
            traj[((size_t)b * KOUT + w) * 2 + 1] = (float)item;
            flp[(size_t)b * KOUT + w] = (orig[item] - lse) + rlp;
            w++;
        }
    }
}

// ---------------- launch ----------------------------------------------------
extern "C" void kernel_launch(void* const* d_in, const int* in_sizes, int n_in,
                              void* d_out, int out_size)
{
    const float* state = (const float*)d_in[0];
    const float* rW1   = (const float*)d_in[1];
    const float* rb1   = (const float*)d_in[2];
    const float* rW2   = (const float*)d_in[3];
    const float* rb2   = (const float*)d_in[4];
    const float* rW3   = (const float*)d_in[5];
    const float* rb3   = (const float*)d_in[6];
    const float* eW1   = (const float*)d_in[7];
    const float* eb1   = (const float*)d_in[8];
    const float* eW2   = (const float*)d_in[9];
    const float* eb2   = (const float*)d_in[10];
    const float* eW3   = (const float*)d_in[11];
    const float* eb3   = (const float*)d_in[12];
    float* out = (float*)d_out;

    k_zero<<<1, 64>>>();
    k_root_linear<DD, 0, 0><<<dim3(BB / 16, HH / 64), 256>>>(state, rW1, rb1);
    k_root_linear<HH, 1, 1><<<dim3(BB / 16, HH / 64), 256>>>(nullptr, rW2, rb2);
    k_root_head2<<<BB, 256>>>(rW3, rb3);

    k_exp<DD, 4, HH, 0, 0><<<dim3(EE, 4), HH / 4>>>(state, eW1);     // KR=64
    k_red<4, HH, 0><<<(BB * HH / 4) / 256, 256>>>(eb1);
    k_exp<HH, 4, HH, 1, 1><<<dim3(EE, 4), HH / 4>>>(nullptr, eW2);   // KR=128
    k_red<4, HH, 1><<<(BB * HH / 4) / 256, 256>>>(eb2);
    k_exp<HH, 8, NLF, 2, 2><<<dim3(EE, 8), NLF / 4>>>(nullptr, eW3); // KR=64
    k_final<<<BB, 256>>>(out, eb3);
}

// round 3
// speedup vs baseline: 2.9702x; 1.6342x over previous
#include <cuda_runtime.h>
#include <math.h>

#define BB   256
#define DD   256
#define HH   512
#define EE   64
#define NLF  1024
#define KOUT 10

// ---------------- scratch (device globals; no allocation allowed) ----------
__device__ float g_Y1[BB * HH];
__device__ float g_Y2[BB * HH];
__device__ float g_h1[BB * HH];
__device__ float g_h2[BB * HH];
__device__ int   g_bidx[BB];
__device__ float g_rootlp[BB];
__device__ int   g_count[EE];
__device__ int   g_slot[EE * BB];
// k-split partial sums (deterministic; no float atomics)
__device__ float g_p1[16 * BB * HH];    // 8 MB
__device__ float g_p2[16 * BB * HH];    // 8 MB
__device__ float g_p3[16 * BB * NLF];   // 16 MB

// ---------------- 0: zero routing counts -----------------------------------
__global__ void k_zero()
{
    if (threadIdx.x < EE) g_count[threadIdx.x] = 0;
}

// ---------------- root dense layers: 512 thr, 2-way k-split in block --------
// grid (B/16, H/64); thread = (e-col 0..63, sample-group 0..3, k-half 0..1)
template <int KDIM, int SRCSEL, int DSTSEL>
__global__ __launch_bounds__(512) void k_rootlin(
    const float* __restrict__ Xin, const float* __restrict__ W,
    const float* __restrict__ bias)
{
    const float* X = (SRCSEL == 0) ? Xin : g_Y1;
    float* Y = (DSTSEL == 0) ? g_Y1 : g_Y2;
    constexpr int KH = KDIM / 2;

    __shared__ float4 sX[16][KDIM / 4];
    __shared__ float  sred[16][64];

    int s0 = blockIdx.x * 16;
    int tx = threadIdx.x & 63;
    int sg = (threadIdx.x >> 6) & 3;
    int kg = threadIdx.x >> 8;
    int o  = blockIdx.y * 64 + tx;

    for (int i = threadIdx.x; i < 16 * (KDIM / 4); i += 512) {
        int s = i / (KDIM / 4), kk = i % (KDIM / 4);
        sX[s][kk] = reinterpret_cast<const float4*>(X + (size_t)(s0 + s) * KDIM)[kk];
    }
    __syncthreads();

    const float* Wp = W + (size_t)kg * KH * HH + o;
    float a0 = 0.f, a1 = 0.f, a2 = 0.f, a3 = 0.f;
#pragma unroll 8
    for (int k4 = 0; k4 < KH / 4; k4++) {
        float w0 = Wp[(size_t)(k4 * 4 + 0) * HH];
        float w1 = Wp[(size_t)(k4 * 4 + 1) * HH];
        float w2 = Wp[(size_t)(k4 * 4 + 2) * HH];
        float w3 = Wp[(size_t)(k4 * 4 + 3) * HH];
        float4 x0 = sX[sg * 4 + 0][kg * (KH / 4) + k4];
        float4 x1 = sX[sg * 4 + 1][kg * (KH / 4) + k4];
        float4 x2 = sX[sg * 4 + 2][kg * (KH / 4) + k4];
        float4 x3 = sX[sg * 4 + 3][kg * (KH / 4) + k4];
        a0 = fmaf(w0, x0.x, a0); a0 = fmaf(w1, x0.y, a0);
        a0 = fmaf(w2, x0.z, a0); a0 = fmaf(w3, x0.w, a0);
        a1 = fmaf(w0, x1.x, a1); a1 = fmaf(w1, x1.y, a1);
        a1 = fmaf(w2, x1.z, a1); a1 = fmaf(w3, x1.w, a1);
        a2 = fmaf(w0, x2.x, a2); a2 = fmaf(w1, x2.y, a2);
        a2 = fmaf(w2, x2.z, a2); a2 = fmaf(w3, x2.w, a2);
        a3 = fmaf(w0, x3.x, a3); a3 = fmaf(w1, x3.y, a3);
        a3 = fmaf(w2, x3.z, a3); a3 = fmaf(w3, x3.w, a3);
    }
    if (kg == 1) {
        sred[sg * 4 + 0][tx] = a0; sred[sg * 4 + 1][tx] = a1;
        sred[sg * 4 + 2][tx] = a2; sred[sg * 4 + 3][tx] = a3;
    }
    __syncthreads();
    if (kg == 0) {
        float bb = bias[o];
        Y[(size_t)(s0 + sg * 4 + 0) * HH + o] = fmaxf(a0 + sred[sg * 4 + 0][tx] + bb, 0.f);
        Y[(size_t)(s0 + sg * 4 + 1) * HH + o] = fmaxf(a1 + sred[sg * 4 + 1][tx] + bb, 0.f);
        Y[(size_t)(s0 + sg * 4 + 2) * HH + o] = fmaxf(a2 + sred[sg * 4 + 2][tx] + bb, 0.f);
        Y[(size_t)(s0 + sg * 4 + 3) * HH + o] = fmaxf(a3 + sred[sg * 4 + 3][tx] + bb, 0.f);
    }
}

// ---------------- root head: 16 samples/block, fused argmax/softmax/routing -
__global__ __launch_bounds__(512) void k_root3(
    const float* __restrict__ W, const float* __restrict__ bias)
{
    constexpr int KH = HH / 2;
    __shared__ float4 sX[16][HH / 4];
    __shared__ float  sred[16][EE];
    __shared__ float  slog[16][EE];

    int s0 = blockIdx.x * 16;
    int e  = threadIdx.x & 63;
    int sg = (threadIdx.x >> 6) & 3;
    int kg = threadIdx.x >> 8;

    for (int i = threadIdx.x; i < 16 * (HH / 4); i += 512) {
        int s = i / (HH / 4), kk = i % (HH / 4);
        sX[s][kk] = reinterpret_cast<const float4*>(g_Y2 + (size_t)(s0 + s) * HH)[kk];
    }
    __syncthreads();

    const float* Wp = W + (size_t)kg * KH * EE + e;
    float a0 = 0.f, a1 = 0.f, a2 = 0.f, a3 = 0.f;
#pragma unroll 8
    for (int k4 = 0; k4 < KH / 4; k4++) {
        float w0 = Wp[(size_t)(k4 * 4 + 0) * EE];
        float w1 = Wp[(size_t)(k4 * 4 + 1) * EE];
        float w2 = Wp[(size_t)(k4 * 4 + 2) * EE];
        float w3 = Wp[(size_t)(k4 * 4 + 3) * EE];
        float4 x0 = sX[sg * 4 + 0][kg * (KH / 4) + k4];
        float4 x1 = sX[sg * 4 + 1][kg * (KH / 4) + k4];
        float4 x2 = sX[sg * 4 + 2][kg * (KH / 4) + k4];
        float4 x3 = sX[sg * 4 + 3][kg * (KH / 4) + k4];
        a0 = fmaf(w0, x0.x, a0); a0 = fmaf(w1, x0.y, a0);
        a0 = fmaf(w2, x0.z, a0); a0 = fmaf(w3, x0.w, a0);
        a1 = fmaf(w0, x1.x, a1); a1 = fmaf(w1, x1.y, a1);
        a1 = fmaf(w2, x1.z, a1); a1 = fmaf(w3, x1.w, a1);
        a2 = fmaf(w0, x2.x, a2); a2 = fmaf(w1, x2.y, a2);
        a2 = fmaf(w2, x2.z, a2); a2 = fmaf(w3, x2.w, a2);
        a3 = fmaf(w0, x3.x, a3); a3 = fmaf(w1, x3.y, a3);
        a3 = fmaf(w2, x3.z, a3); a3 = fmaf(w3, x3.w, a3);
    }
    if (kg == 1) {
        sred[sg * 4 + 0][e] = a0; sred[sg * 4 + 1][e] = a1;
        sred[sg * 4 + 2][e] = a2; sred[sg * 4 + 3][e] = a3;
    }
    __syncthreads();
    if (kg == 0) {
        float bb = bias[e];
        slog[sg * 4 + 0][e] = a0 + sred[sg * 4 + 0][e] + bb;
        slog[sg * 4 + 1][e] = a1 + sred[sg * 4 + 1][e] + bb;
        slog[sg * 4 + 2][e] = a2 + sred[sg * 4 + 2][e] + bb;
        slog[sg * 4 + 3][e] = a3 + sred[sg * 4 + 3][e] + bb;
    }
    __syncthreads();

    if (threadIdx.x < 16) {
        int s = threadIdx.x;
        float mx = slog[s][0];
        int   mi = 0;
        for (int i = 1; i < EE; i++) {
            float v = slog[s][i];
            if (v > mx) { mx = v; mi = i; }      // strict > : ties -> lowest index
        }
        float se = 0.f;
        for (int i = 0; i < EE; i++) se += __expf(slog[s][i] - mx);
        int b = s0 + s;
        g_bidx[b]   = mi;
        g_rootlp[b] = slog[s][mi] - mx - __logf(se);
        int pos = atomicAdd(&g_count[mi], 1);
        g_slot[mi * BB + pos] = b;
    }
}

// ---------------- expert tile core: 4 outputs/thread, float4 weights --------
__device__ __forceinline__ void fma4(float4& a, const float4 w, const float s)
{
    a.x = fmaf(w.x, s, a.x); a.y = fmaf(w.y, s, a.y);
    a.z = fmaf(w.z, s, a.z); a.w = fmaf(w.w, s, a.w);
}

template <int KT, int KR, int OT, int CM>
__device__ __forceinline__ void exp_core(
    const float* __restrict__ W, int o, int sxoff,
    const float4 (*sX)[KR / 4], const int* sB, int ct,
    float* __restrict__ P)
{
    float4 acc[CM];
#pragma unroll
    for (int j = 0; j < CM; j++) acc[j] = make_float4(0.f, 0.f, 0.f, 0.f);

#pragma unroll
    for (int k4 = 0; k4 < KT / 4; k4++) {
        const float* wp = W + (size_t)(k4 * 4) * OT + o;
        float4 w0 = *reinterpret_cast<const float4*>(wp);
        float4 w1 = *reinterpret_cast<const float4*>(wp + OT);
        float4 w2 = *reinterpret_cast<const float4*>(wp + 2 * OT);
        float4 w3 = *reinterpret_cast<const float4*>(wp + 3 * OT);
#pragma unroll
        for (int j = 0; j < CM; j++) {
            float4 x = sX[j][sxoff + k4];
            fma4(acc[j], w0, x.x);
            fma4(acc[j], w1, x.y);
            fma4(acc[j], w2, x.z);
            fma4(acc[j], w3, x.w);
        }
    }
#pragma unroll
    for (int j = 0; j < CM; j++)
        if (j < ct)
            *reinterpret_cast<float4*>(P + (size_t)sB[j] * OT + o) = acc[j];
}

// ---------------- grouped expert dense layer, fine K-split partials ---------
// grid (EE, KS); 256 threads. For OT=512 the block's 2 k-subgroups write to
// different partial slices (no in-block reduce). NPART = KS * KSUB = 16.
template <int KDIM, int KS, int OT, int SRC, int DST>
__global__ __launch_bounds__(256) void k_exp(
    const float* __restrict__ Xin, const float* __restrict__ Wsrc)
{
    constexpr int OTH  = OT / 4;        // output threads: 128 or 256
    constexpr int KSUB = 256 / OTH;     // 2 or 1
    constexpr int KR   = KDIM / KS;     // block k-range
    constexpr int KT   = KR / KSUB;     // per-subgroup k-range

    const float* X = (SRC == 0) ? Xin : ((SRC == 1) ? g_h1 : g_h2);
    float* Pbase = (DST == 0) ? g_p1 : ((DST == 1) ? g_p2 : g_p3);

    int ex = blockIdx.x, ks = blockIdx.y;
    int c = g_count[ex];
    if (c == 0) return;

    int ot = threadIdx.x % OTH;
    int kg = threadIdx.x / OTH;
    int o  = ot * 4;
    int sxoff = kg * (KT / 4);

    const float* W = Wsrc + (size_t)ex * KDIM * OT + (size_t)(ks * KR + kg * KT) * OT;
    float* P = Pbase + (size_t)(ks * KSUB + kg) * BB * OT;

    __shared__ float4 sX[8][KR / 4];
    __shared__ int    sB[8];

    for (int st = 0; st < c; st += 8) {
        int ct = min(8, c - st);
        __syncthreads();
        if (threadIdx.x < 8)
            sB[threadIdx.x] = g_slot[ex * BB + st + ((threadIdx.x < ct) ? threadIdx.x : 0)];
        __syncthreads();
        for (int i = threadIdx.x; i < 8 * (KR / 4); i += 256) {
            int s = i / (KR / 4), kk = i % (KR / 4);
            sX[s][kk] = *reinterpret_cast<const float4*>(
                X + (size_t)sB[s] * KDIM + ks * KR + kk * 4);
        }
        __syncthreads();

        if (ct <= 4) exp_core<KT, KR, OT, 4>(W, o, sxoff, sX, sB, ct, P);
        else         exp_core<KT, KR, OT, 8>(W, o, sxoff, sX, sB, ct, P);
    }
}

// ---------------- reduce partials + bias + relu -----------------------------
template <int NP, int OT, int DST>
__global__ __launch_bounds__(256) void k_red(const float* __restrict__ ebias)
{
    const float* Pb = (DST == 0) ? g_p1 : g_p2;
    float* Y = (DST == 0) ? g_h1 : g_h2;
    int idx = blockIdx.x * 256 + threadIdx.x;          // float4 index
    const int row4 = OT / 4;
    int b = idx / row4, o4 = idx % row4;
    int o = o4 * 4;

    float4 s = *reinterpret_cast<const float4*>(Pb + (size_t)b * OT + o);
#pragma unroll
    for (int p = 1; p < NP; p++) {
        float4 v = *reinterpret_cast<const float4*>(Pb + ((size_t)p * BB + b) * OT + o);
        s.x += v.x; s.y += v.y; s.z += v.z; s.w += v.w;
    }
    float4 bb = *reinterpret_cast<const float4*>(ebias + (size_t)g_bidx[b] * OT + o);
    s.x = fmaxf(s.x + bb.x, 0.f);
    s.y = fmaxf(s.y + bb.y, 0.f);
    s.z = fmaxf(s.z + bb.z, 0.f);
    s.w = fmaxf(s.w + bb.w, 0.f);
    *reinterpret_cast<float4*>(Y + (size_t)b * OT + o) = s;
}

// ---------------- final: fuse L3 reduce + log_softmax + top-11 + emit -------
__global__ __launch_bounds__(256) void k_final(
    float* __restrict__ out, const float* __restrict__ eb3)
{
    int b = blockIdx.x;
    __shared__ float sv[NLF];
    __shared__ float orig[NLF];
    __shared__ float rv[256];
    __shared__ int   ri[256];
    __shared__ int   chosen[KOUT + 1];

    int branch = g_bidx[b];

    float lmax = -INFINITY;
    for (int i = threadIdx.x; i < NLF; i += 256) {
        float v = eb3[(size_t)branch * NLF + i];
#pragma unroll
        for (int p = 0; p < 16; p++)
            v += g_p3[((size_t)p * BB + b) * NLF + i];
        sv[i] = v;
        orig[i] = v;
        lmax = fmaxf(lmax, v);
    }
    rv[threadIdx.x] = lmax;
    __syncthreads();
    for (int off = 128; off > 0; off >>= 1) {
        if (threadIdx.x < off) rv[threadIdx.x] = fmaxf(rv[threadIdx.x], rv[threadIdx.x + off]);
        __syncthreads();
    }
    float mx = rv[0];
    __syncthreads();

    float lsum = 0.f;
    for (int i = threadIdx.x; i < NLF; i += 256) lsum += __expf(sv[i] - mx);
    rv[threadIdx.x] = lsum;
    __syncthreads();
    for (int off = 128; off > 0; off >>= 1) {
        if (threadIdx.x < off) rv[threadIdx.x] += rv[threadIdx.x + off];
        __syncthreads();
    }
    float lse = mx + __logf(rv[0]);
    __syncthreads();

    // iterative masked argmax: value desc, ties -> lowest index (matches top_k)
    for (int t = 0; t < KOUT + 1; t++) {
        float bv = -INFINITY;
        int   bi = NLF;
        for (int i = threadIdx.x; i < NLF; i += 256) {
            float v = sv[i];
            if (v > bv) { bv = v; bi = i; }    // ascending scan keeps lowest idx
        }
        rv[threadIdx.x] = bv;
        ri[threadIdx.x] = bi;
        __syncthreads();
        for (int off = 128; off > 0; off >>= 1) {
            if (threadIdx.x < off) {
                float v2 = rv[threadIdx.x + off];
                int   i2 = ri[threadIdx.x + off];
                if (v2 > rv[threadIdx.x] ||
                    (v2 == rv[threadIdx.x] && i2 < ri[threadIdx.x])) {
                    rv[threadIdx.x] = v2;
                    ri[threadIdx.x] = i2;
                }
            }
            __syncthreads();
        }
        if (threadIdx.x == 0) {
            chosen[t] = ri[0];
            sv[ri[0]] = -INFINITY;
        }
        __syncthreads();
    }

    if (threadIdx.x == 0) {
        float rlp   = g_rootlp[b];
        float* traj = out;                    // [B][K][2] as float
        float* flp  = out + BB * KOUT * 2;    // [B][K]
        int w = 0;
        for (int t = 0; t < KOUT + 1 && w < KOUT; t++) {
            int item = chosen[t];
            if (item == 0 && branch == 0) continue;   // drop id-0 trajectory
            traj[((size_t)b * KOUT + w) * 2 + 0] = (float)branch;
            traj[((size_t)b * KOUT + w) * 2 + 1] = (float)item;
            flp[(size_t)b * KOUT + w] = (orig[item] - lse) + rlp;
            w++;
        }
    }
}

// ---------------- launch ----------------------------------------------------
extern "C" void kernel_launch(void* const* d_in, const int* in_sizes, int n_in,
                              void* d_out, int out_size)
{
    const float* state = (const float*)d_in[0];
    const float* rW1   = (const float*)d_in[1];
    const float* rb1   = (const float*)d_in[2];
    const float* rW2   = (const float*)d_in[3];
    const float* rb2   = (const float*)d_in[4];
    const float* rW3   = (const float*)d_in[5];
    const float* rb3   = (const float*)d_in[6];
    const float* eW1   = (const float*)d_in[7];
    const float* eb1   = (const float*)d_in[8];
    const float* eW2   = (const float*)d_in[9];
    const float* eb2   = (const float*)d_in[10];
    const float* eW3   = (const float*)d_in[11];
    const float* eb3   = (const float*)d_in[12];
    float* out = (float*)d_out;

    k_zero<<<1, 64>>>();
    k_rootlin<DD, 0, 0><<<dim3(BB / 16, HH / 64), 512>>>(state, rW1, rb1);
    k_rootlin<HH, 1, 1><<<dim3(BB / 16, HH / 64), 512>>>(nullptr, rW2, rb2);
    k_root3<<<BB / 16, 512>>>(rW3, rb3);

    k_exp<DD,  8, HH, 0, 0><<<dim3(EE,  8), 256>>>(state,  eW1);  // 512 blk, KT=16
    k_red<16, HH, 0><<<(BB * HH / 4) / 256, 256>>>(eb1);
    k_exp<HH,  8, HH, 1, 1><<<dim3(EE,  8), 256>>>(nullptr, eW2); // 512 blk, KT=32
    k_red<16, HH, 1><<<(BB * HH / 4) / 256, 256>>>(eb2);
    k_exp<HH, 16, NLF, 2, 2><<<dim3(EE, 16), 256>>>(nullptr, eW3); // 1024 blk, KT=32
    k_final<<<BB, 256>>>(out, eb3);
}

// round 4
// speedup vs baseline: 3.6608x; 1.2325x over previous
#include <cuda_runtime.h>
#include <math.h>

#define BB   256
#define DD   256
#define HH   512
#define EE   64
#define NLF  1024
#define KOUT 10

// ---------------- scratch (device globals; no allocation allowed) ----------
__device__ float g_Y1[BB * HH];
__device__ float g_Y2[BB * HH];
__device__ float g_h1[BB * HH];
__device__ float g_h2[BB * HH];
__device__ int   g_bidx[BB];
__device__ float g_rootlp[BB];
__device__ int   g_count[EE];
__device__ int   g_slot[EE * BB];
__device__ float g_rp[4 * BB * EE];     // root-head k-split partials
// expert k-split partial sums (deterministic; no float atomics)
__device__ float g_p1[8 * BB * HH];     // 4 MB
__device__ float g_p2[8 * BB * HH];     // 4 MB
__device__ float g_p3[8 * BB * NLF];    // 8 MB

// ---------------- orderable packing helpers ---------------------------------
__device__ __forceinline__ unsigned int fkey(float v)
{
    unsigned int b = __float_as_uint(v);
    return (b & 0x80000000u) ? ~b : (b | 0x80000000u);
}
__device__ __forceinline__ float funkey(unsigned int b)
{
    return __uint_as_float((b & 0x80000000u) ? (b & 0x7FFFFFFFu) : ~b);
}

// ---------------- root dense layers: 8 samples/block, 2-way k-split ---------
// grid (B/8, H/64), 512 thr: e(64) x sg(4, 2 samples each) x kg(2)
template <int KDIM, int SRCSEL, int DSTSEL, bool ZERO>
__global__ __launch_bounds__(512) void k_rootlin(
    const float* __restrict__ Xin, const float* __restrict__ W,
    const float* __restrict__ bias)
{
    const float* X = (SRCSEL == 0) ? Xin : g_Y1;
    float* Y = (DSTSEL == 0) ? g_Y1 : g_Y2;
    constexpr int KH = KDIM / 2;

    if (ZERO && blockIdx.x == 0 && blockIdx.y == 0 && threadIdx.x < EE)
        g_count[threadIdx.x] = 0;

    __shared__ float4 sX[8][KDIM / 4];
    __shared__ float  sred[8][64];

    int s0 = blockIdx.x * 8;
    int tx = threadIdx.x & 63;
    int sg = (threadIdx.x >> 6) & 3;
    int kg = threadIdx.x >> 8;
    int o  = blockIdx.y * 64 + tx;

    for (int i = threadIdx.x; i < 8 * (KDIM / 4); i += 512) {
        int s = i / (KDIM / 4), kk = i % (KDIM / 4);
        sX[s][kk] = reinterpret_cast<const float4*>(X + (size_t)(s0 + s) * KDIM)[kk];
    }
    __syncthreads();

    const float* Wp = W + (size_t)kg * KH * HH + o;
    float a0 = 0.f, a1 = 0.f;
    int sa = sg * 2, sb = sg * 2 + 1;
#pragma unroll 8
    for (int k4 = 0; k4 < KH / 4; k4++) {
        float w0 = Wp[(size_t)(k4 * 4 + 0) * HH];
        float w1 = Wp[(size_t)(k4 * 4 + 1) * HH];
        float w2 = Wp[(size_t)(k4 * 4 + 2) * HH];
        float w3 = Wp[(size_t)(k4 * 4 + 3) * HH];
        float4 x0 = sX[sa][kg * (KH / 4) + k4];
        float4 x1 = sX[sb][kg * (KH / 4) + k4];
        a0 = fmaf(w0, x0.x, a0); a0 = fmaf(w1, x0.y, a0);
        a0 = fmaf(w2, x0.z, a0); a0 = fmaf(w3, x0.w, a0);
        a1 = fmaf(w0, x1.x, a1); a1 = fmaf(w1, x1.y, a1);
        a1 = fmaf(w2, x1.z, a1); a1 = fmaf(w3, x1.w, a1);
    }
    if (kg == 1) { sred[sa][tx] = a0; sred[sb][tx] = a1; }
    __syncthreads();
    if (kg == 0) {
        float bb = bias[o];
        Y[(size_t)(s0 + sa) * HH + o] = fmaxf(a0 + sred[sa][tx] + bb, 0.f);
        Y[(size_t)(s0 + sb) * HH + o] = fmaxf(a1 + sred[sb][tx] + bb, 0.f);
    }
}

// ---------------- root head GEMM: k-split partials ---------------------------
// grid (B/16, 4), 512 thr: e(64) x sj(8, 2 samples each); KH = HH/4 = 128
__global__ __launch_bounds__(512) void k_rootgemm(const float* __restrict__ W)
{
    constexpr int KH = HH / 4;
    __shared__ float4 sX[16][KH / 4];   // 8 KB

    int s0 = blockIdx.x * 16;
    int kq = blockIdx.y;
    int e  = threadIdx.x & 63;
    int sj = threadIdx.x >> 6;

    for (int i = threadIdx.x; i < 16 * (KH / 4); i += 512) {
        int s = i / (KH / 4), kk = i % (KH / 4);
        sX[s][kk] = reinterpret_cast<const float4*>(
            g_Y2 + (size_t)(s0 + s) * HH + kq * KH)[kk];
    }
    __syncthreads();

    const float* Wp = W + (size_t)kq * KH * EE + e;
    float a0 = 0.f, a1 = 0.f;
    int sa = sj * 2, sb = sj * 2 + 1;
#pragma unroll 8
    for (int k4 = 0; k4 < KH / 4; k4++) {
        float w0 = Wp[(size_t)(k4 * 4 + 0) * EE];
        float w1 = Wp[(size_t)(k4 * 4 + 1) * EE];
        float w2 = Wp[(size_t)(k4 * 4 + 2) * EE];
        float w3 = Wp[(size_t)(k4 * 4 + 3) * EE];
        float4 x0 = sX[sa][k4];
        float4 x1 = sX[sb][k4];
        a0 = fmaf(w0, x0.x, a0); a0 = fmaf(w1, x0.y, a0);
        a0 = fmaf(w2, x0.z, a0); a0 = fmaf(w3, x0.w, a0);
        a1 = fmaf(w0, x1.x, a1); a1 = fmaf(w1, x1.y, a1);
        a1 = fmaf(w2, x1.z, a1); a1 = fmaf(w3, x1.w, a1);
    }
    g_rp[(size_t)kq * BB * EE + (size_t)(s0 + sa) * EE + e] = a0;
    g_rp[(size_t)kq * BB * EE + (size_t)(s0 + sb) * EE + e] = a1;
}

// ---------------- root routing: warp per 4 samples, packed-u64 argmax -------
// grid (B/32), 256 thr (8 warps); lane covers experts {l, l+32}
__global__ __launch_bounds__(256) void k_route(const float* __restrict__ bias)
{
    int w = threadIdx.x >> 5;
    int l = threadIdx.x & 31;

    for (int q = 0; q < 4; q++) {
        int b = blockIdx.x * 32 + w * 4 + q;
        int e0 = l, e1 = l + 32;
        float v0 = bias[e0], v1 = bias[e1];
#pragma unroll
        for (int p = 0; p < 4; p++) {
            v0 += g_rp[(size_t)p * BB * EE + (size_t)b * EE + e0];
            v1 += g_rp[(size_t)p * BB * EE + (size_t)b * EE + e1];
        }
        unsigned long long k0 = ((unsigned long long)fkey(v0) << 32) | (unsigned int)(EE - 1 - e0);
        unsigned long long k1 = ((unsigned long long)fkey(v1) << 32) | (unsigned int)(EE - 1 - e1);
        unsigned long long best = max(k0, k1);
#pragma unroll
        for (int off = 16; off > 0; off >>= 1) {
            unsigned long long o2 = __shfl_down_sync(0xFFFFFFFFu, best, off);
            best = max(best, o2);
        }
        best = __shfl_sync(0xFFFFFFFFu, best, 0);
        float mx = funkey((unsigned int)(best >> 32));
        int   mi = EE - 1 - (int)(best & 0xFFFFFFFFu);

        float se = __expf(v0 - mx) + __expf(v1 - mx);
#pragma unroll
        for (int off = 16; off > 0; off >>= 1)
            se += __shfl_down_sync(0xFFFFFFFFu, se, off);

        if (l == 0) {
            g_bidx[b]   = mi;
            g_rootlp[b] = -__logf(se);       // lp at argmax = -log(sum exp(v-mx))
            int pos = atomicAdd(&g_count[mi], 1);
            g_slot[mi * BB + pos] = b;
        }
    }
}

// ---------------- expert fma helper -----------------------------------------
__device__ __forceinline__ void fma4(float4& a, const float4 w, const float s)
{
    a.x = fmaf(w.x, s, a.x); a.y = fmaf(w.y, s, a.y);
    a.z = fmaf(w.z, s, a.z); a.w = fmaf(w.w, s, a.w);
}

// ---------------- grouped expert dense layer, balanced z tiles ---------------
// grid (EE, KS, NZ); 256 thr. Tile = 4 samples; block z handles tiles z, z+NZ...
// For OT=512 the 2 in-block k-subgroups write different partial slices.
template <int KDIM, int KS, int OT, int SRC, int DST, int NZ>
__global__ __launch_bounds__(256) void k_exp(
    const float* __restrict__ Xin, const float* __restrict__ Wsrc)
{
    constexpr int OTH  = OT / 4;        // 128 or 256
    constexpr int KSUB = 256 / OTH;     // 2 or 1
    constexpr int KR   = KDIM / KS;
    constexpr int KT   = KR / KSUB;

    const float* X = (SRC == 0) ? Xin : ((SRC == 1) ? g_h1 : g_h2);
    float* Pbase = (DST == 0) ? g_p1 : ((DST == 1) ? g_p2 : g_p3);

    int ex = blockIdx.x, ks = blockIdx.y, z = blockIdx.z;
    int c = g_count[ex];
    if (z * 4 >= c) return;

    int ot = threadIdx.x % OTH;
    int kg = threadIdx.x / OTH;
    int o  = ot * 4;
    int sxoff = kg * (KT / 4);

    const float* W = Wsrc + (size_t)ex * KDIM * OT + (size_t)(ks * KR + kg * KT) * OT;
    float* P = Pbase + (size_t)(ks * KSUB + kg) * BB * OT;

    __shared__ float4 sX[4][KR / 4];
    __shared__ int    sB[4];

    for (int st = z * 4; st < c; st += NZ * 4) {
        int ct = min(4, c - st);
        __syncthreads();
        if (threadIdx.x < 4)
            sB[threadIdx.x] = g_slot[ex * BB + st + ((threadIdx.x < ct) ? threadIdx.x : 0)];
        __syncthreads();
        for (int i = threadIdx.x; i < 4 * (KR / 4); i += 256) {
            int s = i / (KR / 4), kk = i % (KR / 4);
            sX[s][kk] = *reinterpret_cast<const float4*>(
                X + (size_t)sB[s] * KDIM + ks * KR + kk * 4);
        }
        __syncthreads();

        float4 acc[4];
#pragma unroll
        for (int j = 0; j < 4; j++) acc[j] = make_float4(0.f, 0.f, 0.f, 0.f);

#pragma unroll 8
        for (int k4 = 0; k4 < KT / 4; k4++) {
            const float* wp = W + (size_t)(k4 * 4) * OT + o;
            float4 w0 = *reinterpret_cast<const float4*>(wp);
            float4 w1 = *reinterpret_cast<const float4*>(wp + OT);
            float4 w2 = *reinterpret_cast<const float4*>(wp + 2 * OT);
            float4 w3 = *reinterpret_cast<const float4*>(wp + 3 * OT);
#pragma unroll
            for (int j = 0; j < 4; j++) {
                float4 x = sX[j][sxoff + k4];
                fma4(acc[j], w0, x.x);
                fma4(acc[j], w1, x.y);
                fma4(acc[j], w2, x.z);
                fma4(acc[j], w3, x.w);
            }
        }
#pragma unroll
        for (int j = 0; j < 4; j++)
            if (j < ct)
                *reinterpret_cast<float4*>(P + (size_t)sB[j] * OT + o) = acc[j];
    }
}

// ---------------- reduce 8 partials + bias + relu ----------------------------
template <int OT, int DST>
__global__ __launch_bounds__(256) void k_red(const float* __restrict__ ebias)
{
    const float* Pb = (DST == 0) ? g_p1 : g_p2;
    float* Y = (DST == 0) ? g_h1 : g_h2;
    int idx = blockIdx.x * 256 + threadIdx.x;          // float4 index
    const int row4 = OT / 4;
    int b = idx / row4, o4 = idx % row4;
    int o = o4 * 4;

    float4 s = *reinterpret_cast<const float4*>(Pb + (size_t)b * OT + o);
#pragma unroll
    for (int p = 1; p < 8; p++) {
        float4 v = *reinterpret_cast<const float4*>(Pb + ((size_t)p * BB + b) * OT + o);
        s.x += v.x; s.y += v.y; s.z += v.z; s.w += v.w;
    }
    float4 bb = *reinterpret_cast<const float4*>(ebias + (size_t)g_bidx[b] * OT + o);
    s.x = fmaxf(s.x + bb.x, 0.f);
    s.y = fmaxf(s.y + bb.y, 0.f);
    s.z = fmaxf(s.z + bb.z, 0.f);
    s.w = fmaxf(s.w + bb.w, 0.f);
    *reinterpret_cast<float4*>(Y + (size_t)b * OT + o) = s;
}

// ---------------- final: L3 reduce + log_softmax + top-11 (u64) + emit ------
__global__ __launch_bounds__(256) void k_final(
    float* __restrict__ out, const float* __restrict__ eb3)
{
    int b = blockIdx.x;
    __shared__ float sv[NLF];
    __shared__ float orig[NLF];
    __shared__ unsigned long long swarp[8];
    __shared__ float sred[8];
    __shared__ float smx, slse;
    __shared__ int   chosen[KOUT + 1];

    int branch = g_bidx[b];
    int wid = threadIdx.x >> 5;
    int lane = threadIdx.x & 31;

    for (int i = threadIdx.x; i < NLF; i += 256) {
        float v = eb3[(size_t)branch * NLF + i];
#pragma unroll
        for (int p = 0; p < 8; p++)
            v += g_p3[((size_t)p * BB + b) * NLF + i];
        sv[i] = v;
        orig[i] = v;
    }
    __syncthreads();

    // top-(K+1) passes; pass 0 doubles as softmax max
    for (int t = 0; t < KOUT + 1; t++) {
        unsigned long long best = 0ULL;
        for (int i = threadIdx.x; i < NLF; i += 256)
            best = max(best, ((unsigned long long)fkey(sv[i]) << 32) |
                             (unsigned int)(NLF - 1 - i));
#pragma unroll
        for (int off = 16; off > 0; off >>= 1) {
            unsigned long long o2 = __shfl_down_sync(0xFFFFFFFFu, best, off);
            best = max(best, o2);
        }
        if (lane == 0) swarp[wid] = best;
        __syncthreads();
        if (threadIdx.x == 0) {
            unsigned long long bb = swarp[0];
#pragma unroll
            for (int i2 = 1; i2 < 8; i2++) bb = max(bb, swarp[i2]);
            int idx = NLF - 1 - (int)(bb & 0xFFFFFFFFu);
            chosen[t] = idx;
            sv[idx] = -INFINITY;
            if (t == 0) smx = funkey((unsigned int)(bb >> 32));
        }
        __syncthreads();

        if (t == 0) {   // compute lse once, using orig (pre-mask) values
            float mx = smx;
            float ls = 0.f;
            for (int i = threadIdx.x; i < NLF; i += 256)
                ls += __expf(orig[i] - mx);
#pragma unroll
            for (int off = 16; off > 0; off >>= 1)
                ls += __shfl_down_sync(0xFFFFFFFFu, ls, off);
            if (lane == 0) sred[wid] = ls;
            __syncthreads();
            if (threadIdx.x == 0) {
                float tot = 0.f;
#pragma unroll
                for (int i2 = 0; i2 < 8; i2++) tot += sred[i2];
                slse = mx + __logf(tot);
            }
            __syncthreads();
        }
    }

    if (threadIdx.x == 0) {
        float rlp   = g_rootlp[b];
        float lse   = slse;
        float* traj = out;                    // [B][K][2] as float
        float* flp  = out + BB * KOUT * 2;    // [B][K]
        int w = 0;
        for (int t = 0; t < KOUT + 1 && w < KOUT; t++) {
            int item = chosen[t];
            if (item == 0 && branch == 0) continue;   // drop id-0 trajectory
            traj[((size_t)b * KOUT + w) * 2 + 0] = (float)branch;
            traj[((size_t)b * KOUT + w) * 2 + 1] = (float)item;
            flp[(size_t)b * KOUT + w] = (orig[item] - lse) + rlp;
            w++;
        }
    }
}

// ---------------- launch ----------------------------------------------------
extern "C" void kernel_launch(void* const* d_in, const int* in_sizes, int n_in,
                              void* d_out, int out_size)
{
    const float* state = (const float*)d_in[0];
    const float* rW1   = (const float*)d_in[1];
    const float* rb1   = (const float*)d_in[2];
    const float* rW2   = (const float*)d_in[3];
    const float* rb2   = (const float*)d_in[4];
    const float* rW3   = (const float*)d_in[5];
    const float* rb3   = (const float*)d_in[6];
    const float* eW1   = (const float*)d_in[7];
    const float* eb1   = (const float*)d_in[8];
    const float* eW2   = (const float*)d_in[9];
    const float* eb2   = (const float*)d_in[10];
    const float* eW3   = (const float*)d_in[11];
    const float* eb3   = (const float*)d_in[12];
    float* out = (float*)d_out;

    k_rootlin<DD, 0, 0, true ><<<dim3(BB / 8, HH / 64), 512>>>(state, rW1, rb1);
    k_rootlin<HH, 1, 1, false><<<dim3(BB / 8, HH / 64), 512>>>(nullptr, rW2, rb2);
    k_rootgemm<<<dim3(BB / 16, 4), 512>>>(rW3);
    k_route<<<BB / 32, 256>>>(rb3);

    k_exp<DD, 4, HH,  0, 0, 4><<<dim3(EE, 4, 4), 256>>>(state,  eW1);
    k_red<HH, 0><<<(BB * HH / 4) / 256, 256>>>(eb1);
    k_exp<HH, 4, HH,  1, 1, 4><<<dim3(EE, 4, 4), 256>>>(nullptr, eW2);
    k_red<HH, 1><<<(BB * HH / 4) / 256, 256>>>(eb2);
    k_exp<HH, 8, NLF, 2, 2, 4><<<dim3(EE, 8, 4), 256>>>(nullptr, eW3);
    k_final<<<BB, 256>>>(out, eb3);
}